// round 3
// baseline (speedup 1.0000x reference)
#include <cuda_runtime.h>

#define NB 4
#define NA 100000
#define NM 32
#define NC 80
#define CHUNK 256                    // anchors per block
#define NBLK_X ((NA + CHUNK - 1) / CHUNK)   // 391
#define TOTAL_BLOCKS (NBLK_X * NB)          // 1564

// accumulators: [0]=cls_sum, [1]=reg_sum, [2]=num_pos   (zero-init at load,
// reset by the finalizing block at the end of every call)
__device__ double g_acc[3];
__device__ unsigned int g_count;     // zero-init, reset by finalizing block

__device__ __forceinline__ float warp_sum(float v) {
    #pragma unroll
    for (int o = 16; o > 0; o >>= 1) v += __shfl_down_sync(0xffffffffu, v, o);
    return v;
}

__device__ __forceinline__ float huber(float x) {
    float d = fabsf(x);
    return (d < (1.0f / 9.0f)) ? 4.5f * d * d : d - (0.5f / 9.0f);
}

__global__ __launch_bounds__(CHUNK) void fused_loss_kernel(
    const float4* __restrict__ cls,        // (B, A, 80) as float4
    const float4* __restrict__ regression, // (B, A) float4
    const float4* __restrict__ anchors,    // (A) float4
    const float*  __restrict__ annotations,// (B, M, 5)
    float* __restrict__ out)
{
    __shared__ float sb[NM * 5];
    __shared__ int   smeta[CHUNK];   // bits 0..6 class, bit7 pos, bit8 valid
    __shared__ float sred[24];

    const int b  = blockIdx.y;
    const int a0 = blockIdx.x * CHUNK;
    const int tid = threadIdx.x;
    const int n_anchor = min(CHUNK, NA - a0);

    for (int i = tid; i < NM * 5; i += CHUNK)
        sb[i] = annotations[b * NM * 5 + i];
    __syncthreads();

    // ---- Phase A: per-anchor targets ----
    float reg_c = 0.0f, pos_f = 0.0f;
    if (tid < n_anchor) {
        const int a = a0 + tid;
        float4 an = anchors[a];
        float area_a = (an.z - an.x) * (an.w - an.y);
        float best_iou = -1.0f;
        int best = 0;
        #pragma unroll
        for (int m = 0; m < NM; m++) {
            float x1 = sb[m * 5 + 0], y1 = sb[m * 5 + 1];
            float x2 = sb[m * 5 + 2], y2 = sb[m * 5 + 3];
            float iw = fminf(an.z, x2) - fmaxf(an.x, x1);
            float ih = fminf(an.w, y2) - fmaxf(an.y, y1);
            float inter = fmaxf(iw, 0.0f) * fmaxf(ih, 0.0f);
            float uni = area_a + (x2 - x1) * (y2 - y1) - inter;
            float iou = inter / fmaxf(uni, 1e-8f);
            if (iou > best_iou) { best_iou = iou; best = m; }
        }
        bool pos = best_iou >= 0.5f;
        bool ign = (best_iou > 0.4f) && !pos;
        float cx = (an.x + an.z) * 0.5f;
        float cy = (an.y + an.w) * 0.5f;
        bool inside = (cx >= 0.0f) && (cx < 800.0f) && (cy >= 0.0f) && (cy < 800.0f);
        bool valid = inside && !ign;
        int bcls = (int)sb[best * 5 + 4];
        bool is_pos = inside && pos;
        smeta[tid] = (is_pos ? (bcls | 0x80) : 0) | (valid ? 0x100 : 0);

        if (is_pos) {
            pos_f = 1.0f;
            float aw = an.z - an.x, ah = an.w - an.y;
            float t0 = ((sb[best * 5 + 0] - an.x) / aw) * 5.0f;
            float t1 = ((sb[best * 5 + 1] - an.y) / ah) * 5.0f;
            float t2 = ((sb[best * 5 + 2] - an.z) / aw) * 5.0f;
            float t3 = ((sb[best * 5 + 3] - an.w) / ah) * 5.0f;
            float4 r = regression[b * NA + a];
            reg_c = huber(r.x - t0) + huber(r.y - t1) + huber(r.z - t2) + huber(r.w - t3);
        }
    }
    __syncthreads();

    // ---- Phase B: stream this block's classification slab ----
    // slab = n_anchor * 80 floats = n_anchor * 20 float4s, contiguous
    const float4* slab = cls + (size_t)(b * NA + a0) * 20;
    const int n4 = n_anchor * 20;
    float cls_acc = 0.0f;

    #pragma unroll 4
    for (int i = tid; i < n4; i += CHUNK) {
        int al = i / 20;                 // local anchor
        int meta = smeta[al];
        if (!(meta & 0x100)) continue;   // invalid: zero contribution, skip load
        int lc = (meta & 0x80) ? (meta & 0x7F) : -2;
        int cbase = (i - al * 20) * 4;
        float4 v = slab[i];
        float pv[4] = {v.x, v.y, v.z, v.w};
        #pragma unroll
        for (int j = 0; j < 4; j++) {
            float p = fminf(fmaxf(pv[j], 1e-4f), 1.0f - 1e-4f);
            bool is1 = (cbase + j) == lc;
            float x  = is1 ? p : (1.0f - p);   // log argument
            float w  = is1 ? 0.25f : 0.75f;    // alpha
            float om = 1.0f - x;
            cls_acc += w * om * om * (-__logf(x));
        }
    }

    // ---- Phase C: block reduce, 3 double atomics ----
    float wc = warp_sum(cls_acc);
    float wr = warp_sum(reg_c);
    float wp = warp_sum(pos_f);
    int wid = tid >> 5, lane = tid & 31;
    if (lane == 0) { sred[wid] = wc; sred[8 + wid] = wr; sred[16 + wid] = wp; }
    __syncthreads();
    if (wid == 0) {
        float vc = (lane < 8) ? sred[lane] : 0.0f;
        float vr = (lane < 8) ? sred[8 + lane] : 0.0f;
        float vp = (lane < 8) ? sred[16 + lane] : 0.0f;
        vc = warp_sum(vc); vr = warp_sum(vr); vp = warp_sum(vp);
        if (lane == 0) {
            atomicAdd(&g_acc[0], (double)vc);
            if (vr != 0.0f) atomicAdd(&g_acc[1], (double)vr);
            if (vp != 0.0f) atomicAdd(&g_acc[2], (double)vp);
            __threadfence();
            unsigned int done = atomicAdd(&g_count, 1u);
            if (done == TOTAL_BLOCKS - 1) {
                // last block: finalize, write output, reset state for next call
                double np = g_acc[2];
                if (np < 1.0) np = 1.0;
                out[0] = (float)((g_acc[0] + g_acc[1]) / np);
                g_acc[0] = 0.0; g_acc[1] = 0.0; g_acc[2] = 0.0;
                __threadfence();
                g_count = 0u;
            }
        }
    }
}

extern "C" void kernel_launch(void* const* d_in, const int* in_sizes, int n_in,
                              void* d_out, int out_size) {
    const float* cls = (const float*)d_in[0];  // (B, A, 80)
    const float* reg = (const float*)d_in[1];  // (B, A, 4)
    const float* anc = (const float*)d_in[2];  // (A, 4)
    const float* ann = (const float*)d_in[3];  // (B, M, 5)

    dim3 grid(NBLK_X, NB);
    fused_loss_kernel<<<grid, CHUNK>>>(
        (const float4*)cls, (const float4*)reg, (const float4*)anc, ann,
        (float*)d_out);
}

// round 4
// speedup vs baseline: 1.0272x; 1.0272x over previous
#include <cuda_runtime.h>

#define NB 4
#define NA 100000
#define NM 32
#define NC 80
#define TPB 320                      // 16 anchors * 20 float4 per iter
#define CHUNK 320                    // anchors per block (1 per thread in Phase A)
#define NBLK_X ((NA + CHUNK - 1) / CHUNK)   // 313
#define TOTAL_BLOCKS (NBLK_X * NB)          // 1252
#define NEG_W (-0.51986038543f)      /* -0.75 * ln(2) */
#define POS_W (-0.17328679514f)      /* -0.25 * ln(2) */

// accumulators: [0]=cls_sum, [1]=reg_sum, [2]=num_pos (zero-init; reset by finalizer)
__device__ double g_acc[3];
__device__ unsigned int g_count;

__device__ __forceinline__ float warp_sum(float v) {
    #pragma unroll
    for (int o = 16; o > 0; o >>= 1) v += __shfl_down_sync(0xffffffffu, v, o);
    return v;
}

__device__ __forceinline__ float huber(float x) {
    float d = fabsf(x);
    return (d < (1.0f / 9.0f)) ? 4.5f * d * d : d - (0.5f / 9.0f);
}

__device__ __forceinline__ float clampp(float v) {
    return fminf(fmaxf(v, 1.0e-4f), 1.0f - 1.0e-4f);
}

__global__ __launch_bounds__(TPB) void fused_loss_kernel(
    const float*  __restrict__ cls_f,      // (B, A, 80)
    const float4* __restrict__ regression, // (B, A)
    const float4* __restrict__ anchors,    // (A)
    const float*  __restrict__ annotations,// (B, M, 5)
    float* __restrict__ out)
{
    __shared__ float sb[NM * 5];
    __shared__ float sws[CHUNK];     // per-anchor weight: valid ? NEG_W : 0
    __shared__ float sred[32];

    const int b   = blockIdx.y;
    const int a0  = blockIdx.x * CHUNK;
    const int tid = threadIdx.x;
    const int n_anchor = min(CHUNK, NA - a0);

    for (int i = tid; i < NM * 5; i += TPB)
        sb[i] = annotations[b * NM * 5 + i];
    __syncthreads();

    // ---- Phase A: targets, reg loss, and positive-class correction ----
    float reg_c = 0.0f, pos_f = 0.0f, cls_acc = 0.0f;
    if (tid < n_anchor) {
        const int a = a0 + tid;
        float4 an = anchors[a];
        float area_a = (an.z - an.x) * (an.w - an.y);
        float best_iou = -1.0f;
        int best = 0;
        #pragma unroll
        for (int m = 0; m < NM; m++) {
            float x1 = sb[m * 5 + 0], y1 = sb[m * 5 + 1];
            float x2 = sb[m * 5 + 2], y2 = sb[m * 5 + 3];
            float iw = fminf(an.z, x2) - fmaxf(an.x, x1);
            float ih = fminf(an.w, y2) - fmaxf(an.y, y1);
            float inter = fmaxf(iw, 0.0f) * fmaxf(ih, 0.0f);
            float uni = area_a + (x2 - x1) * (y2 - y1) - inter;
            float iou = inter / fmaxf(uni, 1e-8f);
            if (iou > best_iou) { best_iou = iou; best = m; }
        }
        bool pos = best_iou >= 0.5f;
        bool ign = (best_iou > 0.4f) && !pos;
        float cx = (an.x + an.z) * 0.5f;
        float cy = (an.y + an.w) * 0.5f;
        bool inside = (cx >= 0.0f) && (cx < 800.0f) && (cy >= 0.0f) && (cy < 800.0f);
        bool valid = inside && !ign;
        bool is_pos = inside && pos;          // is_pos implies valid
        sws[tid] = valid ? NEG_W : 0.0f;

        if (is_pos) {
            pos_f = 1.0f;
            float aw = an.z - an.x, ah = an.w - an.y;
            float t0 = ((sb[best * 5 + 0] - an.x) / aw) * 5.0f;
            float t1 = ((sb[best * 5 + 1] - an.y) / ah) * 5.0f;
            float t2 = ((sb[best * 5 + 2] - an.z) / aw) * 5.0f;
            float t3 = ((sb[best * 5 + 3] - an.w) / ah) * 5.0f;
            float4 r = regression[(size_t)b * NA + a];
            reg_c = huber(r.x - t0) + huber(r.y - t1) + huber(r.z - t2) + huber(r.w - t3);

            // correction for the one target-class element of this anchor:
            //   add true positive term, subtract the negative term Phase B will add
            int lc = (int)sb[best * 5 + 4];
            float p = clampp(cls_f[((size_t)b * NA + a) * NC + lc]);
            float q = 1.0f - p;
            cls_acc = POS_W * q * q * __log2f(p) - NEG_W * p * p * __log2f(q);
        }
    } else if (tid < CHUNK) {
        sws[tid] = 0.0f;
    }
    __syncthreads();

    // ---- Phase B: stream classification slab with negative-class formula ----
    // float4 index within slab = tid + iter*TPB (pure sequential)
    // local anchor            = tid/20 + iter*16
    const float4* slab = (const float4*)(cls_f + ((size_t)b * NA + a0) * NC) + tid;
    int al = tid / 20;

    if (n_anchor == CHUNK) {
        #pragma unroll 4
        for (int iter = 0; iter < 20; iter++) {
            float ws = sws[al];
            float4 v = __ldcs(slab);
            slab += TPB; al += 16;
            float p0 = clampp(v.x), p1 = clampp(v.y), p2 = clampp(v.z), p3 = clampp(v.w);
            float t0 = p0 * p0 * __log2f(1.0f - p0);
            float t1 = p1 * p1 * __log2f(1.0f - p1);
            float t2 = p2 * p2 * __log2f(1.0f - p2);
            float t3 = p3 * p3 * __log2f(1.0f - p3);
            cls_acc = fmaf(t0 + t1 + t2 + t3, ws, cls_acc);
        }
    } else {
        // partial tail block (last x-block): guard the loads
        for (int iter = 0; iter < 20; iter++) {
            if (al < n_anchor) {
                float ws = sws[al];
                float4 v = __ldcs(slab);
                float p0 = clampp(v.x), p1 = clampp(v.y), p2 = clampp(v.z), p3 = clampp(v.w);
                float t0 = p0 * p0 * __log2f(1.0f - p0);
                float t1 = p1 * p1 * __log2f(1.0f - p1);
                float t2 = p2 * p2 * __log2f(1.0f - p2);
                float t3 = p3 * p3 * __log2f(1.0f - p3);
                cls_acc = fmaf(t0 + t1 + t2 + t3, ws, cls_acc);
            }
            slab += TPB; al += 16;
        }
    }

    // ---- Phase C: block reduce (10 warps), 3 double atomics, last-block finalize ----
    float wc = warp_sum(cls_acc);
    float wr = warp_sum(reg_c);
    float wp = warp_sum(pos_f);
    int wid = tid >> 5, lane = tid & 31;
    if (lane == 0) { sred[wid] = wc; sred[10 + wid] = wr; sred[20 + wid] = wp; }
    __syncthreads();
    if (wid == 0) {
        float vc = (lane < 10) ? sred[lane] : 0.0f;
        float vr = (lane < 10) ? sred[10 + lane] : 0.0f;
        float vp = (lane < 10) ? sred[20 + lane] : 0.0f;
        vc = warp_sum(vc); vr = warp_sum(vr); vp = warp_sum(vp);
        if (lane == 0) {
            atomicAdd(&g_acc[0], (double)vc);
            if (vr != 0.0f) atomicAdd(&g_acc[1], (double)vr);
            if (vp != 0.0f) atomicAdd(&g_acc[2], (double)vp);
            __threadfence();
            unsigned int done = atomicAdd(&g_count, 1u);
            if (done == TOTAL_BLOCKS - 1) {
                double np = g_acc[2];
                if (np < 1.0) np = 1.0;
                out[0] = (float)((g_acc[0] + g_acc[1]) / np);
                g_acc[0] = 0.0; g_acc[1] = 0.0; g_acc[2] = 0.0;
                __threadfence();
                g_count = 0u;
            }
        }
    }
}

extern "C" void kernel_launch(void* const* d_in, const int* in_sizes, int n_in,
                              void* d_out, int out_size) {
    const float* cls = (const float*)d_in[0];  // (B, A, 80)
    const float* reg = (const float*)d_in[1];  // (B, A, 4)
    const float* anc = (const float*)d_in[2];  // (A, 4)
    const float* ann = (const float*)d_in[3];  // (B, M, 5)

    dim3 grid(NBLK_X, NB);
    fused_loss_kernel<<<grid, TPB>>>(
        cls, (const float4*)reg, (const float4*)anc, ann, (float*)d_out);
}

// round 5
// speedup vs baseline: 1.5350x; 1.4944x over previous
#include <cuda_runtime.h>

#define NB 4
#define NA 100000
#define NM 32
#define NC 80
#define N4 (NB * NA * NC / 4)          // 8,000,000 float4s
#define K1_TPB 512
#define K1_BX ((NA + K1_TPB - 1) / K1_TPB)   // 196
#define K2_TPB 256
#define K2_GRID 1184                    // 8 * 148
#define K2_STRIDE (K2_TPB * K2_GRID)
#define NEG_W (-0.51986038543f)         /* -0.75 * ln(2) */
#define POS_W (-0.17328679514f)         /* -0.25 * ln(2) */
#define PMAX (1.0f - 1.0e-4f)

// [0]=cls_sum, [1]=reg_sum, [2]=num_pos  (zero-init; reset by K2 finalizer)
__device__ double g_acc[3];
__device__ unsigned int g_count;
__device__ float g_ws[NB * NA];         // per-anchor weight for the streaming pass

__device__ __forceinline__ float warp_sum(float v) {
    #pragma unroll
    for (int o = 16; o > 0; o >>= 1) v += __shfl_down_sync(0xffffffffu, v, o);
    return v;
}

__device__ __forceinline__ float huber(float x) {
    float d = fabsf(x);
    return (d < (1.0f / 9.0f)) ? 4.5f * d * d : d - (0.5f / 9.0f);
}

// negative-class focal term for one prob (matches K2's formula EXACTLY)
__device__ __forceinline__ float neg_term(float p) {
    float pu = fminf(p, PMAX);
    return pu * pu * __log2f(1.0f - pu);
}

// ---------------- K1: targets / reg loss / positive correction ----------------
__global__ __launch_bounds__(K1_TPB) void targets_kernel(
    const float4* __restrict__ anchors,
    const float4* __restrict__ regression,
    const float*  __restrict__ cls_f,
    const float*  __restrict__ annotations)
{
    __shared__ float sb[NM * 5];
    __shared__ float sred[48];

    const int b = blockIdx.y;
    const int a = blockIdx.x * K1_TPB + threadIdx.x;
    const int tid = threadIdx.x;

    for (int i = tid; i < NM * 5; i += K1_TPB)
        sb[i] = annotations[b * NM * 5 + i];
    __syncthreads();

    float reg_c = 0.0f, pos_f = 0.0f, corr = 0.0f;
    if (a < NA) {
        float4 an = anchors[a];
        float area_a = (an.z - an.x) * (an.w - an.y);
        // division-free argmax: track (inter, union) of current best
        float ib = -1.0f, ub = 1.0f;
        int best = 0;
        #pragma unroll
        for (int m = 0; m < NM; m++) {
            float x1 = sb[m * 5 + 0], y1 = sb[m * 5 + 1];
            float x2 = sb[m * 5 + 2], y2 = sb[m * 5 + 3];
            float iw = fminf(an.z, x2) - fmaxf(an.x, x1);
            float ih = fminf(an.w, y2) - fmaxf(an.y, y1);
            float inter = fmaxf(iw, 0.0f) * fmaxf(ih, 0.0f);
            float uni = area_a + (x2 - x1) * (y2 - y1) - inter;
            if (inter * ub > ib * uni) { ib = inter; ub = uni; best = m; }
        }
        float best_iou = ib / fmaxf(ub, 1e-8f);

        bool pos = best_iou >= 0.5f;
        bool ign = (best_iou > 0.4f) && !pos;
        float cx = (an.x + an.z) * 0.5f;
        float cy = (an.y + an.w) * 0.5f;
        bool inside = (cx >= 0.0f) && (cx < 800.0f) && (cy >= 0.0f) && (cy < 800.0f);
        bool valid = inside && !ign;
        bool is_pos = inside && pos;

        g_ws[b * NA + a] = valid ? NEG_W : 0.0f;

        if (is_pos) {
            pos_f = 1.0f;
            float aw = an.z - an.x, ah = an.w - an.y;
            float t0 = ((sb[best * 5 + 0] - an.x) / aw) * 5.0f;
            float t1 = ((sb[best * 5 + 1] - an.y) / ah) * 5.0f;
            float t2 = ((sb[best * 5 + 2] - an.z) / aw) * 5.0f;
            float t3 = ((sb[best * 5 + 3] - an.w) / ah) * 5.0f;
            float4 r = regression[(size_t)b * NA + a];
            reg_c = huber(r.x - t0) + huber(r.y - t1) + huber(r.z - t2) + huber(r.w - t3);

            // classification correction for the single target-class element:
            // + true positive-label focal term, − the negative term K2 adds
            int lc = (int)sb[best * 5 + 4];
            float p = cls_f[((size_t)b * NA + a) * NC + lc];
            float pc = fminf(fmaxf(p, 1.0e-4f), PMAX);
            float q = 1.0f - pc;
            corr = POS_W * q * q * __log2f(pc) - NEG_W * neg_term(p);
        }
    }

    float wc = warp_sum(corr);
    float wr = warp_sum(reg_c);
    float wp = warp_sum(pos_f);
    int wid = tid >> 5, lane = tid & 31;
    if (lane == 0) { sred[wid] = wc; sred[16 + wid] = wr; sred[32 + wid] = wp; }
    __syncthreads();
    if (wid == 0) {
        float vc = (lane < 16) ? sred[lane] : 0.0f;
        float vr = (lane < 16) ? sred[16 + lane] : 0.0f;
        float vp = (lane < 16) ? sred[32 + lane] : 0.0f;
        vc = warp_sum(vc); vr = warp_sum(vr); vp = warp_sum(vp);
        if (lane == 0) {
            if (vc != 0.0f) atomicAdd(&g_acc[0], (double)vc);
            if (vr != 0.0f) atomicAdd(&g_acc[1], (double)vr);
            if (vp != 0.0f) atomicAdd(&g_acc[2], (double)vp);
        }
    }
}

// ---------------- K2: branch-free streaming focal pass ----------------
__global__ __launch_bounds__(K2_TPB, 4) void focal_kernel(
    const float4* __restrict__ cls,
    float* __restrict__ out)
{
    __shared__ float sred[8];
    float acc = 0.0f;
    int i = blockIdx.x * K2_TPB + threadIdx.x;

    // main loop: 4 independent (cls, ws) load pairs per batch, front-loaded
    for (; i + 3 * K2_STRIDE < N4; i += 4 * K2_STRIDE) {
        float4 v0 = cls[i];
        float4 v1 = cls[i + K2_STRIDE];
        float4 v2 = cls[i + 2 * K2_STRIDE];
        float4 v3 = cls[i + 3 * K2_STRIDE];
        float w0 = __ldg(&g_ws[(unsigned)i / 20u]);
        float w1 = __ldg(&g_ws[(unsigned)(i + K2_STRIDE) / 20u]);
        float w2 = __ldg(&g_ws[(unsigned)(i + 2 * K2_STRIDE) / 20u]);
        float w3 = __ldg(&g_ws[(unsigned)(i + 3 * K2_STRIDE) / 20u]);
        acc = fmaf(neg_term(v0.x) + neg_term(v0.y) + neg_term(v0.z) + neg_term(v0.w), w0, acc);
        acc = fmaf(neg_term(v1.x) + neg_term(v1.y) + neg_term(v1.z) + neg_term(v1.w), w1, acc);
        acc = fmaf(neg_term(v2.x) + neg_term(v2.y) + neg_term(v2.z) + neg_term(v2.w), w2, acc);
        acc = fmaf(neg_term(v3.x) + neg_term(v3.y) + neg_term(v3.z) + neg_term(v3.w), w3, acc);
    }
    for (; i < N4; i += K2_STRIDE) {
        float4 v = cls[i];
        float w = __ldg(&g_ws[(unsigned)i / 20u]);
        acc = fmaf(neg_term(v.x) + neg_term(v.y) + neg_term(v.z) + neg_term(v.w), w, acc);
    }

    float ws_ = warp_sum(acc);
    int wid = threadIdx.x >> 5, lane = threadIdx.x & 31;
    if (lane == 0) sred[wid] = ws_;
    __syncthreads();
    if (wid == 0) {
        float v = (lane < 8) ? sred[lane] : 0.0f;
        v = warp_sum(v);
        if (lane == 0) {
            atomicAdd(&g_acc[0], (double)v);
            __threadfence();
            unsigned int done = atomicAdd(&g_count, 1u);
            if (done == K2_GRID - 1) {
                double np = g_acc[2];
                if (np < 1.0) np = 1.0;
                out[0] = (float)((g_acc[0] + g_acc[1]) / np);
                g_acc[0] = 0.0; g_acc[1] = 0.0; g_acc[2] = 0.0;
                __threadfence();
                g_count = 0u;
            }
        }
    }
}

extern "C" void kernel_launch(void* const* d_in, const int* in_sizes, int n_in,
                              void* d_out, int out_size) {
    const float* cls = (const float*)d_in[0];  // (B, A, 80)
    const float* reg = (const float*)d_in[1];  // (B, A, 4)
    const float* anc = (const float*)d_in[2];  // (A, 4)
    const float* ann = (const float*)d_in[3];  // (B, M, 5)

    dim3 grid1(K1_BX, NB);
    targets_kernel<<<grid1, K1_TPB>>>(
        (const float4*)anc, (const float4*)reg, cls, ann);

    focal_kernel<<<K2_GRID, K2_TPB>>>((const float4*)cls, (float*)d_out);
}

// round 6
// speedup vs baseline: 1.8849x; 1.2279x over previous
#include <cuda_runtime.h>

#define NB 4
#define NA 100000
#define NM 32
#define NC 80
#define TPB 256
#define NBLK_X ((NA + TPB - 1) / TPB)     // 391
#define TOTAL_BLOCKS (NBLK_X * NB)        // 1564
#define NEG_W (-0.51986038543f)           /* -0.75 * ln(2) */
#define POS_W (-0.17328679514f)           /* -0.25 * ln(2) */
#define PMAX (1.0f - 1.0e-4f)

// [0]=cls_sum, [1]=reg_sum, [2]=num_pos  (zero-init; reset by finalizer block)
__device__ double g_acc[3];
__device__ unsigned int g_count;

__device__ __forceinline__ float warp_sum(float v) {
    #pragma unroll
    for (int o = 16; o > 0; o >>= 1) v += __shfl_down_sync(0xffffffffu, v, o);
    return v;
}

__device__ __forceinline__ float huber(float x) {
    float d = fabsf(x);
    return (d < (1.0f / 9.0f)) ? 4.5f * d * d : d - (0.5f / 9.0f);
}

// negative-class focal term (weight applied by caller)
__device__ __forceinline__ float nt(float p) {
    float pu = fminf(p, PMAX);
    return pu * pu * __log2f(1.0f - pu);
}

__device__ __forceinline__ float sum4(float4 v) {
    return (nt(v.x) + nt(v.y)) + (nt(v.z) + nt(v.w));
}

__global__ __launch_bounds__(TPB) void fused_loss_kernel(
    const float*  __restrict__ cls_f,      // (B, A, 80)
    const float4* __restrict__ regression, // (B, A)
    const float4* __restrict__ anchors,    // (A)
    const float*  __restrict__ annotations,// (B, M, 5)
    float* __restrict__ out)
{
    __shared__ float4 sb4[NM];    // box coords
    __shared__ float  sarea[NM];  // box areas
    __shared__ float  scls[NM];   // box classes
    __shared__ float  sred[24];

    const int b   = blockIdx.y;
    const int tid = threadIdx.x;
    const int a   = blockIdx.x * TPB + tid;
    const bool active = (a < NA);

    if (tid < NM) {
        const float* ap = annotations + (b * NM + tid) * 5;
        float x1 = ap[0], y1 = ap[1], x2 = ap[2], y2 = ap[3];
        sb4[tid]   = make_float4(x1, y1, x2, y2);
        sarea[tid] = (x2 - x1) * (y2 - y1);
        scls[tid]  = ap[4];
    }
    __syncthreads();

    // ---- prefetch first cls batch (overlaps IoU compute with DRAM latency) ----
    const float4* cp = (const float4*)cls_f + ((size_t)b * NA + (active ? a : 0)) * 20;
    float4 v0 = cp[0], v1 = cp[1], v2 = cp[2], v3 = cp[3];

    // ---- Phase A: IoU argmax (division-free), targets ----
    float reg_c = 0.0f, pos_f = 0.0f, w = 0.0f;
    int best = 0;
    bool is_pos = false;
    float4 an = anchors[active ? a : 0];
    {
        float area_a = (an.z - an.x) * (an.w - an.y);
        float ib = -1.0f, ub = 1.0f;
        #pragma unroll
        for (int m = 0; m < NM; m++) {
            float4 bx = sb4[m];
            float iw = fminf(an.z, bx.z) - fmaxf(an.x, bx.x);
            float ih = fminf(an.w, bx.w) - fmaxf(an.y, bx.y);
            float inter = fmaxf(iw, 0.0f) * fmaxf(ih, 0.0f);
            float uni = area_a + sarea[m] - inter;
            if (inter * ub > ib * uni) { ib = inter; ub = uni; best = m; }
        }
        float best_iou = ib / fmaxf(ub, 1e-8f);
        bool pos = best_iou >= 0.5f;
        bool ign = (best_iou > 0.4f) && !pos;
        float cx = (an.x + an.z) * 0.5f;
        float cy = (an.y + an.w) * 0.5f;
        bool inside = (cx >= 0.0f) && (cx < 800.0f) && (cy >= 0.0f) && (cy < 800.0f);
        bool valid = inside && !ign;
        is_pos = inside && pos && active;
        w = (valid && active) ? NEG_W : 0.0f;
    }

    // ---- Phase B: stream this anchor's 80 classification probs ----
    float s = sum4(v0) + sum4(v1) + sum4(v2) + sum4(v3);
    #pragma unroll
    for (int batch = 1; batch < 5; batch++) {
        float4 u0 = cp[batch * 4 + 0];
        float4 u1 = cp[batch * 4 + 1];
        float4 u2 = cp[batch * 4 + 2];
        float4 u3 = cp[batch * 4 + 3];
        s += sum4(u0) + sum4(u1) + sum4(u2) + sum4(u3);
    }
    float cls_acc = w * s;

    // ---- positive-anchor extras (rare path) ----
    if (is_pos) {
        pos_f = 1.0f;
        float4 bx = sb4[best];
        float aw = an.z - an.x, ah = an.w - an.y;
        float t0 = ((bx.x - an.x) / aw) * 5.0f;
        float t1 = ((bx.y - an.y) / ah) * 5.0f;
        float t2 = ((bx.z - an.z) / aw) * 5.0f;
        float t3 = ((bx.w - an.w) / ah) * 5.0f;
        float4 r = regression[(size_t)b * NA + a];
        reg_c = huber(r.x - t0) + huber(r.y - t1) + huber(r.z - t2) + huber(r.w - t3);

        // correction: + true positive-label term, − the negative term added above
        int lc = (int)scls[best];
        float p = cls_f[((size_t)b * NA + a) * NC + lc];   // L1 hit
        float pc = fminf(fmaxf(p, 1.0e-4f), PMAX);
        float q = 1.0f - pc;
        cls_acc += POS_W * q * q * __log2f(pc) - NEG_W * nt(p);
    }

    // ---- Phase C: block reduce (8 warps), 3 double atomics, last-block finalize ----
    float wc = warp_sum(cls_acc);
    float wr = warp_sum(reg_c);
    float wp = warp_sum(pos_f);
    int wid = tid >> 5, lane = tid & 31;
    if (lane == 0) { sred[wid] = wc; sred[8 + wid] = wr; sred[16 + wid] = wp; }
    __syncthreads();
    if (wid == 0) {
        float vc = (lane < 8) ? sred[lane] : 0.0f;
        float vr = (lane < 8) ? sred[8 + lane] : 0.0f;
        float vp = (lane < 8) ? sred[16 + lane] : 0.0f;
        vc = warp_sum(vc); vr = warp_sum(vr); vp = warp_sum(vp);
        if (lane == 0) {
            atomicAdd(&g_acc[0], (double)vc);
            if (vr != 0.0f) atomicAdd(&g_acc[1], (double)vr);
            if (vp != 0.0f) atomicAdd(&g_acc[2], (double)vp);
            __threadfence();
            unsigned int done = atomicAdd(&g_count, 1u);
            if (done == TOTAL_BLOCKS - 1) {
                double np = g_acc[2];
                if (np < 1.0) np = 1.0;
                out[0] = (float)((g_acc[0] + g_acc[1]) / np);
                g_acc[0] = 0.0; g_acc[1] = 0.0; g_acc[2] = 0.0;
                __threadfence();
                g_count = 0u;
            }
        }
    }
}

extern "C" void kernel_launch(void* const* d_in, const int* in_sizes, int n_in,
                              void* d_out, int out_size) {
    const float* cls = (const float*)d_in[0];  // (B, A, 80)
    const float* reg = (const float*)d_in[1];  // (B, A, 4)
    const float* anc = (const float*)d_in[2];  // (A, 4)
    const float* ann = (const float*)d_in[3];  // (B, M, 5)

    dim3 grid(NBLK_X, NB);
    fused_loss_kernel<<<grid, TPB>>>(
        cls, (const float4*)reg, (const float4*)anc, ann, (float*)d_out);
}

// round 7
// speedup vs baseline: 2.4959x; 1.3242x over previous
#include <cuda_runtime.h>

#define NB 4
#define NA 100000
#define NM 32
#define NC 80
#define TPB 256
#define NBLK_X ((NA + TPB - 1) / TPB)     // 391
#define TOTAL_BLOCKS (NBLK_X * NB)        // 1564
#define NEG_W (-0.51986038543f)           /* -0.75 * ln(2) */
#define POS_W (-0.17328679514f)           /* -0.25 * ln(2) */
#define PMAX (1.0f - 1.0e-4f)
#define FULL 0xffffffffu

// [0]=cls_sum, [1]=reg_sum, [2]=num_pos  (zero-init; reset by finalizer block)
__device__ double g_acc[3];
__device__ unsigned int g_count;

__device__ __forceinline__ float warp_sum(float v) {
    #pragma unroll
    for (int o = 16; o > 0; o >>= 1) v += __shfl_down_sync(FULL, v, o);
    return v;
}

__device__ __forceinline__ float huber(float x) {
    float d = fabsf(x);
    return (d < (1.0f / 9.0f)) ? 4.5f * d * d : d - (0.5f / 9.0f);
}

// negative-class focal term (weight applied by caller)
__device__ __forceinline__ float nt(float p) {
    float pu = fminf(p, PMAX);
    return pu * pu * __log2f(1.0f - pu);
}

__device__ __forceinline__ float sum4(float4 v) {
    return (nt(v.x) + nt(v.y)) + (nt(v.z) + nt(v.w));
}

__global__ __launch_bounds__(TPB) void fused_loss_kernel(
    const float*  __restrict__ cls_f,      // (B, A, 80)
    const float4* __restrict__ regression, // (B, A)
    const float4* __restrict__ anchors,    // (A)
    const float*  __restrict__ annotations,// (B, M, 5)
    float* __restrict__ out)
{
    __shared__ float4 sb4[NM];    // box coords
    __shared__ float  sarea[NM];  // box areas
    __shared__ float  scls[NM];   // box classes
    __shared__ float  sred[24];

    const int b    = blockIdx.y;
    const int tid  = threadIdx.x;
    const int lane = tid & 31;
    const int wrp  = tid >> 5;
    const int warp_a0 = blockIdx.x * TPB + wrp * 32;  // warp's first anchor
    const int a    = warp_a0 + lane;
    // tail is warp-aligned: every warp is fully active or fully inactive
    const bool wactive = (warp_a0 < NA);

    if (tid < NM) {
        const float* ap = annotations + (b * NM + tid) * 5;
        float x1 = ap[0], y1 = ap[1], x2 = ap[2], y2 = ap[3];
        sb4[tid]   = make_float4(x1, y1, x2, y2);
        sarea[tid] = (x2 - x1) * (y2 - y1);
        scls[tid]  = ap[4];
    }
    __syncthreads();

    // ---- Phase A: per-thread IoU argmax (division-free), targets ----
    float reg_c = 0.0f, pos_f = 0.0f, w = 0.0f, cls_acc = 0.0f;
    int best = 0;
    bool is_pos = false;
    float4 an = make_float4(0.f, 0.f, 0.f, 0.f);
    if (wactive) {
        an = anchors[a];
        float area_a = (an.z - an.x) * (an.w - an.y);
        float ib = -1.0f, ub = 1.0f;
        #pragma unroll
        for (int m = 0; m < NM; m++) {
            float4 bx = sb4[m];
            float iw = fminf(an.z, bx.z) - fmaxf(an.x, bx.x);
            float ih = fminf(an.w, bx.w) - fmaxf(an.y, bx.y);
            float inter = fmaxf(iw, 0.0f) * fmaxf(ih, 0.0f);
            float uni = area_a + sarea[m] - inter;
            if (inter * ub > ib * uni) { ib = inter; ub = uni; best = m; }
        }
        float best_iou = ib / fmaxf(ub, 1e-8f);
        bool pos = best_iou >= 0.5f;
        bool ign = (best_iou > 0.4f) && !pos;
        float cx = (an.x + an.z) * 0.5f;
        float cy = (an.y + an.w) * 0.5f;
        bool inside = (cx >= 0.0f) && (cx < 800.0f) && (cy >= 0.0f) && (cy < 800.0f);
        bool valid = inside && !ign;
        is_pos = inside && pos;
        w = valid ? NEG_W : 0.0f;
    }

    // ---- Phase B: warp-cooperative coalesced stream over 640 float4s ----
    // warp's slab = 32 anchors * 20 float4 = 10KB contiguous; lane l takes l+32k.
    if (wactive) {
        const float4* slab = (const float4*)cls_f + ((size_t)b * NA + warp_a0) * 20;
        float acc = 0.0f;
        #pragma unroll
        for (int k0 = 0; k0 < 20; k0 += 4) {
            const unsigned i0 = lane + 32 * k0;
            const unsigned i1 = i0 + 32, i2 = i0 + 64, i3 = i0 + 96;
            float4 v0 = __ldcs(slab + i0);
            float4 v1 = __ldcs(slab + i1);
            float4 v2 = __ldcs(slab + i2);
            float4 v3 = __ldcs(slab + i3);
            float w0 = __shfl_sync(FULL, w, i0 / 20u);
            float w1 = __shfl_sync(FULL, w, i1 / 20u);
            float w2 = __shfl_sync(FULL, w, i2 / 20u);
            float w3 = __shfl_sync(FULL, w, i3 / 20u);
            acc = fmaf(sum4(v0), w0, acc);
            acc = fmaf(sum4(v1), w1, acc);
            acc = fmaf(sum4(v2), w2, acc);
            acc = fmaf(sum4(v3), w3, acc);
        }
        cls_acc = acc;
    }

    // ---- positive-anchor extras (rare path) ----
    if (is_pos) {
        pos_f = 1.0f;
        float4 bx = sb4[best];
        float aw = an.z - an.x, ah = an.w - an.y;
        float t0 = ((bx.x - an.x) / aw) * 5.0f;
        float t1 = ((bx.y - an.y) / ah) * 5.0f;
        float t2 = ((bx.z - an.z) / aw) * 5.0f;
        float t3 = ((bx.w - an.w) / ah) * 5.0f;
        float4 r = regression[(size_t)b * NA + a];
        reg_c = huber(r.x - t0) + huber(r.y - t1) + huber(r.z - t2) + huber(r.w - t3);

        // correction: + true positive-label term, − the negative term added above
        int lc = (int)scls[best];
        float p = cls_f[((size_t)b * NA + a) * NC + lc];
        float pc = fminf(fmaxf(p, 1.0e-4f), PMAX);
        float q = 1.0f - pc;
        cls_acc += POS_W * q * q * __log2f(pc) - NEG_W * nt(p);
    }

    // ---- Phase C: block reduce (8 warps), 3 double atomics, last-block finalize ----
    float wc = warp_sum(cls_acc);
    float wr = warp_sum(reg_c);
    float wp = warp_sum(pos_f);
    if (lane == 0) { sred[wrp] = wc; sred[8 + wrp] = wr; sred[16 + wrp] = wp; }
    __syncthreads();
    if (wrp == 0) {
        float vc = (lane < 8) ? sred[lane] : 0.0f;
        float vr = (lane < 8) ? sred[8 + lane] : 0.0f;
        float vp = (lane < 8) ? sred[16 + lane] : 0.0f;
        vc = warp_sum(vc); vr = warp_sum(vr); vp = warp_sum(vp);
        if (lane == 0) {
            atomicAdd(&g_acc[0], (double)vc);
            if (vr != 0.0f) atomicAdd(&g_acc[1], (double)vr);
            if (vp != 0.0f) atomicAdd(&g_acc[2], (double)vp);
            __threadfence();
            unsigned int done = atomicAdd(&g_count, 1u);
            if (done == TOTAL_BLOCKS - 1) {
                double np = g_acc[2];
                if (np < 1.0) np = 1.0;
                out[0] = (float)((g_acc[0] + g_acc[1]) / np);
                g_acc[0] = 0.0; g_acc[1] = 0.0; g_acc[2] = 0.0;
                __threadfence();
                g_count = 0u;
            }
        }
    }
}

extern "C" void kernel_launch(void* const* d_in, const int* in_sizes, int n_in,
                              void* d_out, int out_size) {
    const float* cls = (const float*)d_in[0];  // (B, A, 80)
    const float* reg = (const float*)d_in[1];  // (B, A, 4)
    const float* anc = (const float*)d_in[2];  // (A, 4)
    const float* ann = (const float*)d_in[3];  // (B, M, 5)

    dim3 grid(NBLK_X, NB);
    fused_loss_kernel<<<grid, TPB>>>(
        cls, (const float4*)reg, (const float4*)anc, ann, (float*)d_out);
}